// round 15
// baseline (speedup 1.0000x reference)
#include <cuda_runtime.h>
#include <cuda_bf16.h>
#include <cstdint>

// Problem constants
#define BB 4
#define TT 2048
#define CC 1024
#define HH 16
#define DH 64
#define MM (BB*TT)          // 8192 rows for both GEMMs

// ---------------------------------------------------------------------------
// Pre-split bf16 hi/lo planes (device globals; uint4 for 16B alignment)
// ---------------------------------------------------------------------------
__device__ uint4 g_Xh4[MM*CC/8],  g_Xl4[MM*CC/8];          // x          [M][C]
__device__ uint4 g_Wh4[4*CC*CC/8], g_Wl4[4*CC*CC/8];       // W_attn|W_proj
__device__ uint4 g_Qh4[MM*CC/8],  g_Ql4[MM*CC/8];          // Q [B,H,T,D]
__device__ uint4 g_Kh4[MM*CC/8],  g_Kl4[MM*CC/8];
__device__ uint4 g_Vh4[MM*CC/8],  g_Vl4[MM*CC/8];
__device__ uint4 g_Yh4[MM*CC/8],  g_Yl4[MM*CC/8];          // attn out [B,T,C]

typedef __nv_bfloat16 bf16;

// ---------------------------------------------------------------------------
// primitives
// ---------------------------------------------------------------------------
__device__ __forceinline__ uint32_t smem_u32(const void* p) {
    return (uint32_t)__cvta_generic_to_shared(p);
}
__device__ __forceinline__ void ldsm4(uint32_t& r0, uint32_t& r1, uint32_t& r2, uint32_t& r3, uint32_t a) {
    asm volatile("ldmatrix.sync.aligned.m8n8.x4.shared.b16 {%0,%1,%2,%3},[%4];"
                 : "=r"(r0), "=r"(r1), "=r"(r2), "=r"(r3) : "r"(a));
}
__device__ __forceinline__ void ldsm4t(uint32_t& r0, uint32_t& r1, uint32_t& r2, uint32_t& r3, uint32_t a) {
    asm volatile("ldmatrix.sync.aligned.m8n8.x4.trans.shared.b16 {%0,%1,%2,%3},[%4];"
                 : "=r"(r0), "=r"(r1), "=r"(r2), "=r"(r3) : "r"(a));
}
__device__ __forceinline__ void mma16816(float* c, uint32_t a0, uint32_t a1, uint32_t a2, uint32_t a3,
                                         uint32_t b0, uint32_t b1) {
    asm volatile("mma.sync.aligned.m16n8k16.row.col.f32.bf16.bf16.f32 "
                 "{%0,%1,%2,%3},{%4,%5,%6,%7},{%8,%9},{%0,%1,%2,%3};"
                 : "+f"(c[0]), "+f"(c[1]), "+f"(c[2]), "+f"(c[3])
                 : "r"(a0), "r"(a1), "r"(a2), "r"(a3), "r"(b0), "r"(b1));
}
__device__ __forceinline__ void cp16(uint32_t s, const void* g) {
    asm volatile("cp.async.cg.shared.global [%0], [%1], 16;" :: "r"(s), "l"(g));
}
__device__ __forceinline__ void cp_commit() {
    asm volatile("cp.async.commit_group;" ::: "memory");
}
__device__ __forceinline__ void cp_wait1() {
    asm volatile("cp.async.wait_group 1;" ::: "memory");
}
__device__ __forceinline__ uint32_t pack_bf16(float x, float y) {
    __nv_bfloat162 t = __floats2bfloat162_rn(x, y);
    return *(uint32_t*)&t;
}
__device__ __forceinline__ void splitf(float x, float& h, float& l) {
    h = __bfloat162float(__float2bfloat16(x));
    l = x - h;
}
__device__ __forceinline__ void split2(float x, float y, uint32_t& h, uint32_t& l) {
    float hx, lx, hy, ly;
    splitf(x, hx, lx); splitf(y, hy, ly);
    h = pack_bf16(hx, hy);
    l = pack_bf16(lx, ly);
}

// ---------------------------------------------------------------------------
// One-time split: x, W_attn, W_proj -> bf16 hi/lo planes.
// ---------------------------------------------------------------------------
__global__ void convert_kernel(const float* __restrict__ x,
                               const float* __restrict__ W_attn,
                               const float* __restrict__ W_proj)
{
    bf16* Xh = (bf16*)g_Xh4; bf16* Xl = (bf16*)g_Xl4;
    bf16* Wh = (bf16*)g_Wh4; bf16* Wl = (bf16*)g_Wl4;
    const int stride = gridDim.x * blockDim.x;
    const int t0 = blockIdx.x * blockDim.x + threadIdx.x;

    for (int i = t0; i < MM*CC/4; i += stride) {
        float4 v = *(const float4*)&x[(size_t)i*4];
        uint32_t h01, l01, h23, l23;
        split2(v.x, v.y, h01, l01);
        split2(v.z, v.w, h23, l23);
        *(uint2*)&Xh[(size_t)i*4] = make_uint2(h01, h23);
        *(uint2*)&Xl[(size_t)i*4] = make_uint2(l01, l23);
    }
    for (int i = t0; i < 3*CC*CC/4; i += stride) {
        float4 v = *(const float4*)&W_attn[(size_t)i*4];
        uint32_t h01, l01, h23, l23;
        split2(v.x, v.y, h01, l01);
        split2(v.z, v.w, h23, l23);
        *(uint2*)&Wh[(size_t)i*4] = make_uint2(h01, h23);
        *(uint2*)&Wl[(size_t)i*4] = make_uint2(l01, l23);
    }
    for (int i = t0; i < CC*CC/4; i += stride) {
        float4 v = *(const float4*)&W_proj[(size_t)i*4];
        uint32_t h01, l01, h23, l23;
        split2(v.x, v.y, h01, l01);
        split2(v.z, v.w, h23, l23);
        *(uint2*)&Wh[(size_t)(3*CC*CC) + (size_t)i*4] = make_uint2(h01, h23);
        *(uint2*)&Wl[(size_t)(3*CC*CC) + (size_t)i*4] = make_uint2(l01, l23);
    }
}

// ---------------------------------------------------------------------------
// Persistent tensor-core GEMM: grid = 148 CTAs, each walks its tiles with a
// single flattened (tile x ktile) 3-stage cp.async pipeline that never drains
// across tile boundaries (epilogue overlaps the next tile's loads).
// Block tile 128x128x64, 512 threads, 16 warps (4m x 4n), warp tile 32x32.
// ---------------------------------------------------------------------------
#define GEMM_STAGE 65536
#define GEMM_SMEM  (3*GEMM_STAGE)
#define GEMM_GRID  148

__device__ __forceinline__ void gemm_load_tile(uint32_t uS, const bf16* Ah, const bf16* Al,
                                               const bf16* Wh, const bf16* Wl,
                                               int bm, int bn, int k0, int N, int tid)
{
    #pragma unroll
    for (int i = 0; i < 2; i++) {
        const int c  = i * 512 + tid;
        const int m  = c >> 3;
        const int k8 = c & 7;
        const size_t g = (size_t)(bm + m) * CC + k0 + k8 * 8;
        const uint32_t off = m * 128 + ((k8 ^ (m & 7)) << 4);
        cp16(uS + off,         &Ah[g]);
        cp16(uS + 16384 + off, &Al[g]);
    }
    #pragma unroll
    for (int i = 0; i < 2; i++) {
        const int c  = i * 512 + tid;
        const int k  = c >> 4;
        const int n8 = c & 15;
        const size_t g = (size_t)(k0 + k) * N + bn + n8 * 8;
        const uint32_t off = k * 256 + ((n8 ^ (k & 7)) << 4);
        cp16(uS + 32768 + off, &Wh[g]);
        cp16(uS + 49152 + off, &Wl[g]);
    }
}

template<int MODE>
__global__ __launch_bounds__(512) void hgemm_kernel(const float* __restrict__ bias,
                                                    float* __restrict__ out,
                                                    int N)
{
    extern __shared__ char smg[];
    const uint32_t uBase = smem_u32(smg);

    const bf16* Ah = (MODE == 0) ? (const bf16*)g_Xh4 : (const bf16*)g_Yh4;
    const bf16* Al = (MODE == 0) ? (const bf16*)g_Xl4 : (const bf16*)g_Yl4;
    const bf16* Wh = (const bf16*)g_Wh4 + (MODE == 0 ? 0 : (size_t)3*CC*CC);
    const bf16* Wl = (const bf16*)g_Wl4 + (MODE == 0 ? 0 : (size_t)3*CC*CC);

    const int tid  = threadIdx.x;
    const int wid  = tid >> 5;
    const int lane = tid & 31;
    const int warp_m = wid & 3;       // 0..3 -> m offset *32
    const int warp_n = wid >> 2;      // 0..3 -> n offset *32

    const int nbx    = N / 128;
    const int ntiles = nbx * (MM / 128);
    const int G      = gridDim.x;
    const int myT    = (ntiles - (int)blockIdx.x + G - 1) / G;
    if (myT <= 0) return;
    const int total  = myT * 16;      // flattened (tile, ktile) steps

    float acc[2][4][4];
    #pragma unroll
    for (int mt = 0; mt < 2; mt++)
        #pragma unroll
        for (int nt = 0; nt < 4; nt++)
            #pragma unroll
            for (int r = 0; r < 4; r++) acc[mt][nt][r] = 0.f;

    // prologue: steps 0,1 (both within the first tile; myT>=1 -> total>=16)
    {
        const int t0 = blockIdx.x;
        const int bm0 = (t0 / nbx) * 128, bn0 = (t0 % nbx) * 128;
        gemm_load_tile(uBase, Ah, Al, Wh, Wl, bm0, bn0, 0, N, tid);
        cp_commit();
        gemm_load_tile(uBase + GEMM_STAGE, Ah, Al, Wh, Wl, bm0, bn0, 64, N, tid);
        cp_commit();
    }

    for (int s = 0; s < total; s++) {
        cp_wait1();                // step s's loads (issued 2 steps back) done
        __syncthreads();
        if (s + 2 < total) {       // prefetch step s+2 (possibly next tile)
            const int t2 = blockIdx.x + ((s + 2) >> 4) * G;
            gemm_load_tile(uBase + ((s + 2) % 3) * GEMM_STAGE, Ah, Al, Wh, Wl,
                           (t2 / nbx) * 128, (t2 % nbx) * 128,
                           ((s + 2) & 15) * 64, N, tid);
        }
        cp_commit();               // always — keeps group count invariant
        const uint32_t uAh = uBase + (s % 3) * GEMM_STAGE;
        const uint32_t uAl = uAh + 16384;
        const uint32_t uBh = uAh + 32768;
        const uint32_t uBl = uAh + 49152;

        #pragma unroll
        for (int ks = 0; ks < 64; ks += 16) {
            uint32_t ah[2][4], al[2][4];
            #pragma unroll
            for (int mt = 0; mt < 2; mt++) {
                const int m = warp_m * 32 + mt * 16 + (lane & 15);
                const int k = ks + (lane >> 4) * 8;
                const uint32_t off = m * 128 + (((k >> 3) ^ (m & 7)) << 4);
                ldsm4(ah[mt][0], ah[mt][1], ah[mt][2], ah[mt][3], uAh + off);
                ldsm4(al[mt][0], al[mt][1], al[mt][2], al[mt][3], uAl + off);
            }
            uint32_t bhf[4][2], blf[4][2];
            #pragma unroll
            for (int p = 0; p < 2; p++) {
                const int k = ks + ((lane >> 3) & 1) * 8 + (lane & 7);
                const int n = warp_n * 32 + p * 16 + (lane >> 4) * 8;
                const uint32_t off = k * 256 + (((n >> 3) ^ (k & 7)) << 4);
                ldsm4t(bhf[2*p][0], bhf[2*p][1], bhf[2*p+1][0], bhf[2*p+1][1], uBh + off);
                ldsm4t(blf[2*p][0], blf[2*p][1], blf[2*p+1][0], blf[2*p+1][1], uBl + off);
            }
            // term-reordered: consecutive mmas hit different accumulators
            // (per-acc order stays hh -> hl -> lh: numerically identical)
            #pragma unroll
            for (int mt = 0; mt < 2; mt++)
                #pragma unroll
                for (int nt = 0; nt < 4; nt++)
                    mma16816(acc[mt][nt], ah[mt][0], ah[mt][1], ah[mt][2], ah[mt][3],
                             bhf[nt][0], bhf[nt][1]);
            #pragma unroll
            for (int mt = 0; mt < 2; mt++)
                #pragma unroll
                for (int nt = 0; nt < 4; nt++)
                    mma16816(acc[mt][nt], ah[mt][0], ah[mt][1], ah[mt][2], ah[mt][3],
                             blf[nt][0], blf[nt][1]);
            #pragma unroll
            for (int mt = 0; mt < 2; mt++)
                #pragma unroll
                for (int nt = 0; nt < 4; nt++)
                    mma16816(acc[mt][nt], al[mt][0], al[mt][1], al[mt][2], al[mt][3],
                             bhf[nt][0], bhf[nt][1]);
        }

        if ((s & 15) == 15) {
            // ---- epilogue for this tile (overlaps in-flight loads) ----
            const int t  = blockIdx.x + (s >> 4) * G;
            const int bm = (t / nbx) * 128;
            const int bn = (t % nbx) * 128;
            bf16* Qh = (bf16*)g_Qh4; bf16* Ql = (bf16*)g_Ql4;
            bf16* Kh = (bf16*)g_Kh4; bf16* Kl = (bf16*)g_Kl4;
            bf16* Vh = (bf16*)g_Vh4; bf16* Vl = (bf16*)g_Vl4;
            const int g  = lane >> 2;
            const int tg = lane & 3;
            #pragma unroll
            for (int mt = 0; mt < 2; mt++)
                #pragma unroll
                for (int nt = 0; nt < 4; nt++) {
                    const int gn = bn + warp_n * 32 + nt * 8 + tg * 2;
                    #pragma unroll
                    for (int half = 0; half < 2; half++) {
                        const int gm = bm + warp_m * 32 + mt * 16 + g + half * 8;
                        const float v0 = acc[mt][nt][half * 2 + 0] + bias[gn];
                        const float v1 = acc[mt][nt][half * 2 + 1] + bias[gn + 1];
                        if (MODE == 0) {
                            uint32_t hp, lp;
                            split2(v0, v1, hp, lp);
                            const int which = gn >> 10;
                            const int c = gn & 1023;
                            const int h = c >> 6, d = c & 63;
                            const int b = gm >> 11;
                            const int tt = gm & 2047;
                            const size_t idx = ((size_t)((b*HH + h)*TT + tt))*DH + d;
                            if (which == 0)      { *(uint32_t*)&Qh[idx] = hp; *(uint32_t*)&Ql[idx] = lp; }
                            else if (which == 1) { *(uint32_t*)&Kh[idx] = hp; *(uint32_t*)&Kl[idx] = lp; }
                            else                 { *(uint32_t*)&Vh[idx] = hp; *(uint32_t*)&Vl[idx] = lp; }
                        } else {
                            out[(size_t)gm * N + gn    ] = v0;
                            out[(size_t)gm * N + gn + 1] = v1;
                        }
                        acc[mt][nt][half * 2 + 0] = 0.f;
                        acc[mt][nt][half * 2 + 1] = 0.f;
                    }
                }
        }
    }
}

// ---------------------------------------------------------------------------
// Flash attention (tensor-core, FA2 layout), pre-split planes,
// cp.async 3-stage pipelined K/V tiles. Longest-first schedule. Base-2 softmax.
// (unchanged from R12 — proven at 860us)
// ---------------------------------------------------------------------------
#define ATT_STAGE 32768
#define ATT_SMEM  (3*ATT_STAGE)

__device__ __forceinline__ void attn_load_tile(uint32_t uS,
                                               const bf16* Kh, const bf16* Kl,
                                               const bf16* Vh, const bf16* Vl,
                                               int kt, int tid)
{
    #pragma unroll
    for (int i = 0; i < 2; i++) {
        const int c  = i * 256 + tid;
        const int r  = c >> 3;
        const int d8 = c & 7;
        const size_t gg = (size_t)(kt*64 + r) * DH + d8 * 8;
        const uint32_t off = r * 128 + ((d8 ^ (r & 7)) << 4);
        cp16(uS + off,         &Kh[gg]);
        cp16(uS + 8192 + off,  &Kl[gg]);
        cp16(uS + 16384 + off, &Vh[gg]);
        cp16(uS + 24576 + off, &Vl[gg]);
    }
}

__global__ __launch_bounds__(256) void attn3_kernel()
{
    extern __shared__ char smx[];
    const uint32_t uB = smem_u32(smx);

    const int qtb = (TT/128 - 1) - (blockIdx.x >> 6);
    const int bh  = blockIdx.x & 63;
    const int qb  = qtb * 128;
    const int tid = threadIdx.x;
    const int wid = tid >> 5;
    const int lane = tid & 31;

    const bf16* Qh = (const bf16*)g_Qh4 + (size_t)bh * TT * DH;
    const bf16* Ql = (const bf16*)g_Ql4 + (size_t)bh * TT * DH;
    const bf16* Kh = (const bf16*)g_Kh4 + (size_t)bh * TT * DH;
    const bf16* Kl = (const bf16*)g_Kl4 + (size_t)bh * TT * DH;
    const bf16* Vh = (const bf16*)g_Vh4 + (size_t)bh * TT * DH;
    const bf16* Vl = (const bf16*)g_Vl4 + (size_t)bh * TT * DH;

    #pragma unroll
    for (int i = 0; i < 4; i++) {
        const int c  = i * 256 + tid;
        const int m  = c >> 3;
        const int d8 = c & 7;
        const size_t g = (size_t)(qb + m) * DH + d8 * 8;
        const uint32_t off = m * 128 + ((d8 ^ (m & 7)) << 4);
        *(uint4*)(smx + off)         = *(const uint4*)&Qh[g];
        *(uint4*)(smx + 16384 + off) = *(const uint4*)&Ql[g];
    }
    __syncthreads();

    uint32_t qh[4][4], ql[4][4];
    {
        const int m = wid * 16 + (lane & 15);
        #pragma unroll
        for (int ks = 0; ks < 4; ks++) {
            const int k = ks * 16 + (lane >> 4) * 8;
            const uint32_t off = m * 128 + (((k >> 3) ^ (m & 7)) << 4);
            ldsm4(qh[ks][0], qh[ks][1], qh[ks][2], qh[ks][3], uB + off);
            ldsm4(ql[ks][0], ql[ks][1], ql[ks][2], ql[ks][3], uB + 16384 + off);
        }
    }
    __syncthreads();

    float oacc[8][4];
    #pragma unroll
    for (int nt = 0; nt < 8; nt++)
        #pragma unroll
        for (int r = 0; r < 4; r++) oacc[nt][r] = 0.f;
    float m0 = -1e30f, m1 = -1e30f, l0 = 0.f, l1 = 0.f;

    const int qw = qb + wid * 16;
    const int g  = lane >> 2;
    const int tg = lane & 3;
    const int row0 = qw + g;
    const float scale = 0.18033688011f;   // 0.125 * log2(e)
    const int ktmax = 2 * qtb + 1;

    attn_load_tile(uB, Kh, Kl, Vh, Vl, 0, tid);
    cp_commit();
    attn_load_tile(uB + ATT_STAGE, Kh, Kl, Vh, Vl, 1, tid);
    cp_commit();

    int stage = 0;
    for (int kt = 0; kt <= ktmax; kt++) {
        cp_wait1();
        __syncthreads();
        if (kt + 2 <= ktmax) {
            int s2 = stage + 2; if (s2 >= 3) s2 -= 3;
            attn_load_tile(uB + s2 * ATT_STAGE, Kh, Kl, Vh, Vl, kt + 2, tid);
        }
        cp_commit();
        const uint32_t uS = uB + stage * ATT_STAGE;

        if (kt * 64 <= qw + 15) {
            float sacc[8][4];
            #pragma unroll
            for (int nt = 0; nt < 8; nt++)
                #pragma unroll
                for (int r = 0; r < 4; r++) sacc[nt][r] = 0.f;

            #pragma unroll
            for (int ks = 0; ks < 4; ks++) {
                #pragma unroll
                for (int p = 0; p < 4; p++) {
                    const int n = p * 16 + (lane & 15);
                    const int k = ks * 16 + (lane >> 4) * 8;
                    const uint32_t off = n * 128 + (((k >> 3) ^ (n & 7)) << 4);
                    uint32_t b0a, b0b, b1a, b1b;
                    ldsm4(b0a, b0b, b1a, b1b, uS + off);          // Kh
                    mma16816(sacc[2*p  ], qh[ks][0], qh[ks][1], qh[ks][2], qh[ks][3], b0a, b1a);
                    mma16816(sacc[2*p+1], qh[ks][0], qh[ks][1], qh[ks][2], qh[ks][3], b0b, b1b);
                    mma16816(sacc[2*p  ], ql[ks][0], ql[ks][1], ql[ks][2], ql[ks][3], b0a, b1a);
                    mma16816(sacc[2*p+1], ql[ks][0], ql[ks][1], ql[ks][2], ql[ks][3], b0b, b1b);
                    ldsm4(b0a, b0b, b1a, b1b, uS + 8192 + off);   // Kl
                    mma16816(sacc[2*p  ], qh[ks][0], qh[ks][1], qh[ks][2], qh[ks][3], b0a, b1a);
                    mma16816(sacc[2*p+1], qh[ks][0], qh[ks][1], qh[ks][2], qh[ks][3], b0b, b1b);
                }
            }

            if (kt * 64 + 63 > qw) {
                #pragma unroll
                for (int nt = 0; nt < 8; nt++) {
                    const int col = kt * 64 + nt * 8 + tg * 2;
                    sacc[nt][0] = (col     <= row0    ) ? sacc[nt][0] * scale : -1e30f;
                    sacc[nt][1] = (col + 1 <= row0    ) ? sacc[nt][1] * scale : -1e30f;
                    sacc[nt][2] = (col     <= row0 + 8) ? sacc[nt][2] * scale : -1e30f;
                    sacc[nt][3] = (col + 1 <= row0 + 8) ? sacc[nt][3] * scale : -1e30f;
                }
            } else {
                #pragma unroll
                for (int nt = 0; nt < 8; nt++)
                    #pragma unroll
                    for (int r = 0; r < 4; r++) sacc[nt][r] *= scale;
            }

            float mx0 = -1e30f, mx1 = -1e30f;
            #pragma unroll
            for (int nt = 0; nt < 8; nt++) {
                mx0 = fmaxf(mx0, fmaxf(sacc[nt][0], sacc[nt][1]));
                mx1 = fmaxf(mx1, fmaxf(sacc[nt][2], sacc[nt][3]));
            }
            mx0 = fmaxf(mx0, __shfl_xor_sync(0xffffffffu, mx0, 1));
            mx0 = fmaxf(mx0, __shfl_xor_sync(0xffffffffu, mx0, 2));
            mx1 = fmaxf(mx1, __shfl_xor_sync(0xffffffffu, mx1, 1));
            mx1 = fmaxf(mx1, __shfl_xor_sync(0xffffffffu, mx1, 2));
            const float mn0 = fmaxf(m0, mx0);
            const float mn1 = fmaxf(m1, mx1);
            const float corr0 = exp2f(m0 - mn0);
            const float corr1 = exp2f(m1 - mn1);

            uint32_t ph01[8], ph23[8], pl01[8], pl23[8];
            float ps0 = 0.f, ps1 = 0.f;
            #pragma unroll
            for (int nt = 0; nt < 8; nt++) {
                const float p0 = exp2f(sacc[nt][0] - mn0);
                const float p1 = exp2f(sacc[nt][1] - mn0);
                const float p2 = exp2f(sacc[nt][2] - mn1);
                const float p3 = exp2f(sacc[nt][3] - mn1);
                ps0 += p0 + p1;
                ps1 += p2 + p3;
                split2(p0, p1, ph01[nt], pl01[nt]);
                split2(p2, p3, ph23[nt], pl23[nt]);
            }
            ps0 += __shfl_xor_sync(0xffffffffu, ps0, 1);
            ps0 += __shfl_xor_sync(0xffffffffu, ps0, 2);
            ps1 += __shfl_xor_sync(0xffffffffu, ps1, 1);
            ps1 += __shfl_xor_sync(0xffffffffu, ps1, 2);
            l0 = l0 * corr0 + ps0;  m0 = mn0;
            l1 = l1 * corr1 + ps1;  m1 = mn1;
            #pragma unroll
            for (int nt = 0; nt < 8; nt++) {
                oacc[nt][0] *= corr0; oacc[nt][1] *= corr0;
                oacc[nt][2] *= corr1; oacc[nt][3] *= corr1;
            }

            #pragma unroll
            for (int kk = 0; kk < 4; kk++) {
                const uint32_t a0 = ph01[2*kk],   a1 = ph23[2*kk];
                const uint32_t a2 = ph01[2*kk+1], a3 = ph23[2*kk+1];
                const uint32_t c0 = pl01[2*kk],   c1 = pl23[2*kk];
                const uint32_t c2 = pl01[2*kk+1], c3 = pl23[2*kk+1];
                #pragma unroll
                for (int dp = 0; dp < 4; dp++) {
                    const int r = kk * 16 + (lane & 15);
                    const int d = dp * 16 + (lane >> 4) * 8;
                    const uint32_t off = r * 128 + (((d >> 3) ^ (r & 7)) << 4);
                    uint32_t b0a, b1a, b0b, b1b;
                    ldsm4t(b0a, b1a, b0b, b1b, uS + 16384 + off);   // Vh
                    mma16816(oacc[2*dp  ], a0, a1, a2, a3, b0a, b1a);
                    mma16816(oacc[2*dp+1], a0, a1, a2, a3, b0b, b1b);
                    mma16816(oacc[2*dp  ], c0, c1, c2, c3, b0a, b1a);
                    mma16816(oacc[2*dp+1], c0, c1, c2, c3, b0b, b1b);
                    ldsm4t(b0a, b1a, b0b, b1b, uS + 24576 + off);   // Vl
                    mma16816(oacc[2*dp  ], a0, a1, a2, a3, b0a, b1a);
                    mma16816(oacc[2*dp+1], a0, a1, a2, a3, b0b, b1b);
                }
            }
        }
        stage++; if (stage == 3) stage = 0;
    }

    bf16* Yh = (bf16*)g_Yh4;
    bf16* Yl = (bf16*)g_Yl4;
    const float inv0 = 1.0f / l0;
    const float inv1 = 1.0f / l1;
    const int b = bh >> 4, h = bh & 15;
    #pragma unroll
    for (int nt = 0; nt < 8; nt++) {
        const int coln = h * 64 + nt * 8 + tg * 2;
        uint32_t hp, lp;
        split2(oacc[nt][0] * inv0, oacc[nt][1] * inv0, hp, lp);
        *(uint32_t*)&Yh[((size_t)(b*TT + row0))*CC + coln] = hp;
        *(uint32_t*)&Yl[((size_t)(b*TT + row0))*CC + coln] = lp;
        split2(oacc[nt][2] * inv1, oacc[nt][3] * inv1, hp, lp);
        *(uint32_t*)&Yh[((size_t)(b*TT + row0 + 8))*CC + coln] = hp;
        *(uint32_t*)&Yl[((size_t)(b*TT + row0 + 8))*CC + coln] = lp;
    }
}

// ---------------------------------------------------------------------------
extern "C" void kernel_launch(void* const* d_in, const int* in_sizes, int n_in,
                              void* d_out, int out_size)
{
    const float* x      = (const float*)d_in[0];
    const float* b_attn = (const float*)d_in[2];
    const float* b_proj = (const float*)d_in[4];
    float* out = (float*)d_out;

    static bool attr_set = false;
    if (!attr_set) {
        cudaFuncSetAttribute(attn3_kernel,
                             cudaFuncAttributeMaxDynamicSharedMemorySize, ATT_SMEM);
        cudaFuncSetAttribute(hgemm_kernel<0>,
                             cudaFuncAttributeMaxDynamicSharedMemorySize, GEMM_SMEM);
        cudaFuncSetAttribute(hgemm_kernel<1>,
                             cudaFuncAttributeMaxDynamicSharedMemorySize, GEMM_SMEM);
        attr_set = true;
    }

    // 0) one-time fp32 -> bf16 hi/lo split of x and weights
    convert_kernel<<<1024, 256>>>(x, (const float*)d_in[1], (const float*)d_in[3]);
    // 1) QKV GEMM (persistent, flattened pipeline) + split-scatter into Q/K/V
    hgemm_kernel<0><<<GEMM_GRID, 512, GEMM_SMEM>>>(b_attn, nullptr, 3*CC);
    // 2) Causal flash attention (3-stage pipeline, longest-first)
    attn3_kernel<<<TT/128 * BB*HH, 256, ATT_SMEM>>>();
    // 3) Output projection (persistent, flattened pipeline)
    hgemm_kernel<1><<<GEMM_GRID, 512, GEMM_SMEM>>>(b_proj, out, CC);
}

// round 16
// speedup vs baseline: 1.4062x; 1.4062x over previous
#include <cuda_runtime.h>
#include <cuda_fp16.h>
#include <cstdint>

// Problem constants
#define BB 4
#define TT 2048
#define CC 1024
#define HH 16
#define DH 64
#define MM (BB*TT)          // 8192 rows for both GEMMs

// ---------------------------------------------------------------------------
// fp16 planes (device globals; uint4 for 16B alignment)
// A-side operands are split (hi+lo = exact); B-side operands single fp16.
// ---------------------------------------------------------------------------
__device__ uint4 g_Xh4[MM*CC/8],  g_Xl4[MM*CC/8];          // x split  [M][C]
__device__ uint4 g_Wh4[4*CC*CC/8];                         // W_attn|W_proj single
__device__ uint4 g_Qh4[MM*CC/8],  g_Ql4[MM*CC/8];          // Q split [B,H,T,D]
__device__ uint4 g_Kh4[MM*CC/8];                           // K single
__device__ uint4 g_Vh4[MM*CC/8];                           // V single
__device__ uint4 g_Yh4[MM*CC/8],  g_Yl4[MM*CC/8];          // Y split [B,T,C]

typedef __half f16;

// ---------------------------------------------------------------------------
// primitives
// ---------------------------------------------------------------------------
__device__ __forceinline__ uint32_t smem_u32(const void* p) {
    return (uint32_t)__cvta_generic_to_shared(p);
}
__device__ __forceinline__ void ldsm4(uint32_t& r0, uint32_t& r1, uint32_t& r2, uint32_t& r3, uint32_t a) {
    asm volatile("ldmatrix.sync.aligned.m8n8.x4.shared.b16 {%0,%1,%2,%3},[%4];"
                 : "=r"(r0), "=r"(r1), "=r"(r2), "=r"(r3) : "r"(a));
}
__device__ __forceinline__ void ldsm4t(uint32_t& r0, uint32_t& r1, uint32_t& r2, uint32_t& r3, uint32_t a) {
    asm volatile("ldmatrix.sync.aligned.m8n8.x4.trans.shared.b16 {%0,%1,%2,%3},[%4];"
                 : "=r"(r0), "=r"(r1), "=r"(r2), "=r"(r3) : "r"(a));
}
__device__ __forceinline__ void mma16816(float* c, uint32_t a0, uint32_t a1, uint32_t a2, uint32_t a3,
                                         uint32_t b0, uint32_t b1) {
    asm volatile("mma.sync.aligned.m16n8k16.row.col.f32.f16.f16.f32 "
                 "{%0,%1,%2,%3},{%4,%5,%6,%7},{%8,%9},{%0,%1,%2,%3};"
                 : "+f"(c[0]), "+f"(c[1]), "+f"(c[2]), "+f"(c[3])
                 : "r"(a0), "r"(a1), "r"(a2), "r"(a3), "r"(b0), "r"(b1));
}
__device__ __forceinline__ void cp16(uint32_t s, const void* g) {
    asm volatile("cp.async.cg.shared.global [%0], [%1], 16;" :: "r"(s), "l"(g));
}
__device__ __forceinline__ void cp_commit() {
    asm volatile("cp.async.commit_group;" ::: "memory");
}
__device__ __forceinline__ void cp_wait1() {
    asm volatile("cp.async.wait_group 1;" ::: "memory");
}
__device__ __forceinline__ uint32_t pack_h2(float x, float y) {
    __half2 t = __floats2half2_rn(x, y);
    return *(uint32_t*)&t;
}
// exact fp16 split: x = h + l with h = fp16(x), l = fp16(x - h) (~2^-24 exact)
__device__ __forceinline__ void split2h(float x, float y, uint32_t& h, uint32_t& l) {
    float hx = __half2float(__float2half_rn(x));
    float hy = __half2float(__float2half_rn(y));
    h = pack_h2(hx, hy);
    l = pack_h2(x - hx, y - hy);
}

// ---------------------------------------------------------------------------
// One-time convert: x -> fp16 split planes; W -> single fp16 plane.
// ---------------------------------------------------------------------------
__global__ void convert_kernel(const float* __restrict__ x,
                               const float* __restrict__ W_attn,
                               const float* __restrict__ W_proj)
{
    f16* Xh = (f16*)g_Xh4; f16* Xl = (f16*)g_Xl4;
    f16* Wh = (f16*)g_Wh4;
    const int stride = gridDim.x * blockDim.x;
    const int t0 = blockIdx.x * blockDim.x + threadIdx.x;

    for (int i = t0; i < MM*CC/4; i += stride) {
        float4 v = *(const float4*)&x[(size_t)i*4];
        uint32_t h01, l01, h23, l23;
        split2h(v.x, v.y, h01, l01);
        split2h(v.z, v.w, h23, l23);
        *(uint2*)&Xh[(size_t)i*4] = make_uint2(h01, h23);
        *(uint2*)&Xl[(size_t)i*4] = make_uint2(l01, l23);
    }
    for (int i = t0; i < 3*CC*CC/4; i += stride) {
        float4 v = *(const float4*)&W_attn[(size_t)i*4];
        *(uint2*)&Wh[(size_t)i*4] = make_uint2(pack_h2(v.x, v.y), pack_h2(v.z, v.w));
    }
    for (int i = t0; i < CC*CC/4; i += stride) {
        float4 v = *(const float4*)&W_proj[(size_t)i*4];
        *(uint2*)&Wh[(size_t)(3*CC*CC) + (size_t)i*4] =
            make_uint2(pack_h2(v.x, v.y), pack_h2(v.z, v.w));
    }
}

// ---------------------------------------------------------------------------
// Tensor-core GEMM, fp16 2-term split: D = (Ah+Al) * Wfp16.
// Block 128x128x64, 512 threads, 16 warps (4m x 4n), warp tile 32x32.
// Smem: 3 stages x 48KB (Ah16|Al16|Bh16). One sync per k-tile; wait_group 1.
// ---------------------------------------------------------------------------
#define GEMM_STAGE 49152
#define GEMM_SMEM  (3*GEMM_STAGE)

template<int MODE>
__device__ __forceinline__ void gemm_load_tile(uint32_t uS, const f16* Ah, const f16* Al,
                                               const f16* Wh,
                                               int bm, int bn, int k0, int N, int tid)
{
    #pragma unroll
    for (int i = 0; i < 2; i++) {
        const int c  = i * 512 + tid;
        const int m  = c >> 3;
        const int k8 = c & 7;
        const size_t g = (size_t)(bm + m) * CC + k0 + k8 * 8;
        const uint32_t off = m * 128 + ((k8 ^ (m & 7)) << 4);
        cp16(uS + off,         &Ah[g]);
        cp16(uS + 16384 + off, &Al[g]);
    }
    #pragma unroll
    for (int i = 0; i < 2; i++) {
        const int c  = i * 512 + tid;
        const int k  = c >> 4;
        const int n8 = c & 15;
        const size_t g = (size_t)(k0 + k) * N + bn + n8 * 8;
        const uint32_t off = k * 256 + ((n8 ^ (k & 7)) << 4);
        cp16(uS + 32768 + off, &Wh[g]);
    }
}

template<int MODE>
__global__ __launch_bounds__(512) void hgemm_kernel(const float* __restrict__ bias,
                                                    float* __restrict__ out,
                                                    int N)
{
    extern __shared__ char smg[];
    const uint32_t uBase = smem_u32(smg);

    const f16* Ah = (MODE == 0) ? (const f16*)g_Xh4 : (const f16*)g_Yh4;
    const f16* Al = (MODE == 0) ? (const f16*)g_Xl4 : (const f16*)g_Yl4;
    const f16* Wh = (const f16*)g_Wh4 + (MODE == 0 ? 0 : (size_t)3*CC*CC);

    const int bm = blockIdx.y * 128;
    const int bn = blockIdx.x * 128;
    const int tid  = threadIdx.x;
    const int wid  = tid >> 5;
    const int lane = tid & 31;
    const int warp_m = wid & 3;
    const int warp_n = wid >> 2;

    float acc[2][4][4];
    #pragma unroll
    for (int mt = 0; mt < 2; mt++)
        #pragma unroll
        for (int nt = 0; nt < 4; nt++)
            #pragma unroll
            for (int r = 0; r < 4; r++) acc[mt][nt][r] = 0.f;

    // prologue: stages 0,1
    gemm_load_tile<MODE>(uBase, Ah, Al, Wh, bm, bn, 0, N, tid);
    cp_commit();
    gemm_load_tile<MODE>(uBase + GEMM_STAGE, Ah, Al, Wh, bm, bn, 64, N, tid);
    cp_commit();

    const int NT = CC / 64;    // 16
    int stage = 0;
    for (int kt = 0; kt < NT; kt++) {
        cp_wait1();
        __syncthreads();
        if (kt + 2 < NT) {
            int s2 = stage + 2; if (s2 >= 3) s2 -= 3;
            gemm_load_tile<MODE>(uBase + s2 * GEMM_STAGE,
                                 Ah, Al, Wh, bm, bn, (kt + 2) * 64, N, tid);
        }
        cp_commit();
        const uint32_t uAh = uBase + stage * GEMM_STAGE;
        const uint32_t uAl = uAh + 16384;
        const uint32_t uBh = uAh + 32768;

        #pragma unroll
        for (int ks = 0; ks < 64; ks += 16) {
            uint32_t ah[2][4], al[2][4];
            #pragma unroll
            for (int mt = 0; mt < 2; mt++) {
                const int m = warp_m * 32 + mt * 16 + (lane & 15);
                const int k = ks + (lane >> 4) * 8;
                const uint32_t off = m * 128 + (((k >> 3) ^ (m & 7)) << 4);
                ldsm4(ah[mt][0], ah[mt][1], ah[mt][2], ah[mt][3], uAh + off);
                ldsm4(al[mt][0], al[mt][1], al[mt][2], al[mt][3], uAl + off);
            }
            uint32_t bhf[4][2];
            #pragma unroll
            for (int p = 0; p < 2; p++) {
                const int k = ks + ((lane >> 3) & 1) * 8 + (lane & 7);
                const int n = warp_n * 32 + p * 16 + (lane >> 4) * 8;
                const uint32_t off = k * 256 + (((n >> 3) ^ (k & 7)) << 4);
                ldsm4t(bhf[2*p][0], bhf[2*p][1], bhf[2*p+1][0], bhf[2*p+1][1], uBh + off);
            }
            // 2 terms; passes interleaved across accumulators
            #pragma unroll
            for (int mt = 0; mt < 2; mt++)
                #pragma unroll
                for (int nt = 0; nt < 4; nt++)
                    mma16816(acc[mt][nt], ah[mt][0], ah[mt][1], ah[mt][2], ah[mt][3],
                             bhf[nt][0], bhf[nt][1]);
            #pragma unroll
            for (int mt = 0; mt < 2; mt++)
                #pragma unroll
                for (int nt = 0; nt < 4; nt++)
                    mma16816(acc[mt][nt], al[mt][0], al[mt][1], al[mt][2], al[mt][3],
                             bhf[nt][0], bhf[nt][1]);
        }
        stage++; if (stage == 3) stage = 0;
    }

    // ---- epilogue ----
    f16* Qh = (f16*)g_Qh4; f16* Ql = (f16*)g_Ql4;
    f16* Kh = (f16*)g_Kh4; f16* Vh = (f16*)g_Vh4;
    const int g  = lane >> 2;
    const int tg = lane & 3;
    #pragma unroll
    for (int mt = 0; mt < 2; mt++)
        #pragma unroll
        for (int nt = 0; nt < 4; nt++) {
            const int gn = bn + warp_n * 32 + nt * 8 + tg * 2;
            #pragma unroll
            for (int half = 0; half < 2; half++) {
                const int gm = bm + warp_m * 32 + mt * 16 + g + half * 8;
                const float v0 = acc[mt][nt][half * 2 + 0] + bias[gn];
                const float v1 = acc[mt][nt][half * 2 + 1] + bias[gn + 1];
                if (MODE == 0) {
                    const int which = gn >> 10;
                    const int c = gn & 1023;
                    const int h = c >> 6, d = c & 63;     // d even
                    const int b = gm >> 11;
                    const int t = gm & 2047;
                    const size_t idx = ((size_t)((b*HH + h)*TT + t))*DH + d;
                    if (which == 0) {
                        uint32_t hp, lp;
                        split2h(v0, v1, hp, lp);
                        *(uint32_t*)&Qh[idx] = hp;
                        *(uint32_t*)&Ql[idx] = lp;
                    } else if (which == 1) {
                        *(uint32_t*)&Kh[idx] = pack_h2(v0, v1);
                    } else {
                        *(uint32_t*)&Vh[idx] = pack_h2(v0, v1);
                    }
                } else {
                    out[(size_t)gm * N + gn    ] = v0;
                    out[(size_t)gm * N + gn + 1] = v1;
                }
            }
        }
}

// ---------------------------------------------------------------------------
// Flash attention, fp16 2-term: S = (Qh+Ql)*K16; O += (Ph+Pl)*V16.
// Block = 8 warps, 128 queries. K/V tiles: 16KB/stage (Kh 8K | Vh 8K),
// 3-stage cp.async pipeline. Longest-first schedule. Base-2 softmax.
// ---------------------------------------------------------------------------
#define ATT_STAGE 16384
#define ATT_SMEM  (3*ATT_STAGE)

__device__ __forceinline__ void attn_load_tile(uint32_t uS,
                                               const f16* Kh, const f16* Vh,
                                               int kt, int tid)
{
    #pragma unroll
    for (int i = 0; i < 2; i++) {
        const int c  = i * 256 + tid;
        const int r  = c >> 3;
        const int d8 = c & 7;
        const size_t gg = (size_t)(kt*64 + r) * DH + d8 * 8;
        const uint32_t off = r * 128 + ((d8 ^ (r & 7)) << 4);
        cp16(uS + off,        &Kh[gg]);
        cp16(uS + 8192 + off, &Vh[gg]);
    }
}

__global__ __launch_bounds__(256) void attn3_kernel()
{
    extern __shared__ char smx[];
    const uint32_t uB = smem_u32(smx);

    const int qtb = (TT/128 - 1) - (blockIdx.x >> 6);
    const int bh  = blockIdx.x & 63;
    const int qb  = qtb * 128;
    const int tid = threadIdx.x;
    const int wid = tid >> 5;
    const int lane = tid & 31;

    const f16* Qhp = (const f16*)g_Qh4 + (size_t)bh * TT * DH;
    const f16* Qlp = (const f16*)g_Ql4 + (size_t)bh * TT * DH;
    const f16* Khp = (const f16*)g_Kh4 + (size_t)bh * TT * DH;
    const f16* Vhp = (const f16*)g_Vh4 + (size_t)bh * TT * DH;

    // ---- stage Q tile (hi at 0, lo at 16KB; consumed before pipeline) ----
    #pragma unroll
    for (int i = 0; i < 4; i++) {
        const int c  = i * 256 + tid;
        const int m  = c >> 3;
        const int d8 = c & 7;
        const size_t g = (size_t)(qb + m) * DH + d8 * 8;
        const uint32_t off = m * 128 + ((d8 ^ (m & 7)) << 4);
        *(uint4*)(smx + off)         = *(const uint4*)&Qhp[g];
        *(uint4*)(smx + 16384 + off) = *(const uint4*)&Qlp[g];
    }
    __syncthreads();

    uint32_t qh[4][4], ql[4][4];
    {
        const int m = wid * 16 + (lane & 15);
        #pragma unroll
        for (int ks = 0; ks < 4; ks++) {
            const int k = ks * 16 + (lane >> 4) * 8;
            const uint32_t off = m * 128 + (((k >> 3) ^ (m & 7)) << 4);
            ldsm4(qh[ks][0], qh[ks][1], qh[ks][2], qh[ks][3], uB + off);
            ldsm4(ql[ks][0], ql[ks][1], ql[ks][2], ql[ks][3], uB + 16384 + off);
        }
    }
    __syncthreads();   // Q regions free; stages reuse them

    float oacc[8][4];
    #pragma unroll
    for (int nt = 0; nt < 8; nt++)
        #pragma unroll
        for (int r = 0; r < 4; r++) oacc[nt][r] = 0.f;
    float m0 = -1e30f, m1 = -1e30f, l0 = 0.f, l1 = 0.f;

    const int qw = qb + wid * 16;
    const int g  = lane >> 2;
    const int tg = lane & 3;
    const int row0 = qw + g;
    const float scale = 0.18033688011f;   // 0.125 * log2(e)
    const int ktmax = 2 * qtb + 1;

    attn_load_tile(uB, Khp, Vhp, 0, tid);
    cp_commit();
    attn_load_tile(uB + ATT_STAGE, Khp, Vhp, 1, tid);
    cp_commit();

    int stage = 0;
    for (int kt = 0; kt <= ktmax; kt++) {
        cp_wait1();
        __syncthreads();
        if (kt + 2 <= ktmax) {
            int s2 = stage + 2; if (s2 >= 3) s2 -= 3;
            attn_load_tile(uB + s2 * ATT_STAGE, Khp, Vhp, kt + 2, tid);
        }
        cp_commit();
        const uint32_t uS = uB + stage * ATT_STAGE;

        if (kt * 64 <= qw + 15) {
            // ---- S = Q K^T (2 terms) ----
            float sacc[8][4];
            #pragma unroll
            for (int nt = 0; nt < 8; nt++)
                #pragma unroll
                for (int r = 0; r < 4; r++) sacc[nt][r] = 0.f;

            #pragma unroll
            for (int ks = 0; ks < 4; ks++) {
                #pragma unroll
                for (int p = 0; p < 4; p++) {
                    const int n = p * 16 + (lane & 15);
                    const int k = ks * 16 + (lane >> 4) * 8;
                    const uint32_t off = n * 128 + (((k >> 3) ^ (n & 7)) << 4);
                    uint32_t b0a, b0b, b1a, b1b;
                    ldsm4(b0a, b0b, b1a, b1b, uS + off);          // Kh
                    mma16816(sacc[2*p  ], qh[ks][0], qh[ks][1], qh[ks][2], qh[ks][3], b0a, b1a);
                    mma16816(sacc[2*p+1], qh[ks][0], qh[ks][1], qh[ks][2], qh[ks][3], b0b, b1b);
                    mma16816(sacc[2*p  ], ql[ks][0], ql[ks][1], ql[ks][2], ql[ks][3], b0a, b1a);
                    mma16816(sacc[2*p+1], ql[ks][0], ql[ks][1], ql[ks][2], ql[ks][3], b0b, b1b);
                }
            }

            // ---- scale (base-2) + causal mask ----
            if (kt * 64 + 63 > qw) {
                #pragma unroll
                for (int nt = 0; nt < 8; nt++) {
                    const int col = kt * 64 + nt * 8 + tg * 2;
                    sacc[nt][0] = (col     <= row0    ) ? sacc[nt][0] * scale : -1e30f;
                    sacc[nt][1] = (col + 1 <= row0    ) ? sacc[nt][1] * scale : -1e30f;
                    sacc[nt][2] = (col     <= row0 + 8) ? sacc[nt][2] * scale : -1e30f;
                    sacc[nt][3] = (col + 1 <= row0 + 8) ? sacc[nt][3] * scale : -1e30f;
                }
            } else {
                #pragma unroll
                for (int nt = 0; nt < 8; nt++)
                    #pragma unroll
                    for (int r = 0; r < 4; r++) sacc[nt][r] *= scale;
            }

            // ---- online softmax (base-2) ----
            float mx0 = -1e30f, mx1 = -1e30f;
            #pragma unroll
            for (int nt = 0; nt < 8; nt++) {
                mx0 = fmaxf(mx0, fmaxf(sacc[nt][0], sacc[nt][1]));
                mx1 = fmaxf(mx1, fmaxf(sacc[nt][2], sacc[nt][3]));
            }
            mx0 = fmaxf(mx0, __shfl_xor_sync(0xffffffffu, mx0, 1));
            mx0 = fmaxf(mx0, __shfl_xor_sync(0xffffffffu, mx0, 2));
            mx1 = fmaxf(mx1, __shfl_xor_sync(0xffffffffu, mx1, 1));
            mx1 = fmaxf(mx1, __shfl_xor_sync(0xffffffffu, mx1, 2));
            const float mn0 = fmaxf(m0, mx0);
            const float mn1 = fmaxf(m1, mx1);
            const float corr0 = exp2f(m0 - mn0);
            const float corr1 = exp2f(m1 - mn1);

            uint32_t ph01[8], ph23[8], pl01[8], pl23[8];
            float ps0 = 0.f, ps1 = 0.f;
            #pragma unroll
            for (int nt = 0; nt < 8; nt++) {
                const float p0 = exp2f(sacc[nt][0] - mn0);
                const float p1 = exp2f(sacc[nt][1] - mn0);
                const float p2 = exp2f(sacc[nt][2] - mn1);
                const float p3 = exp2f(sacc[nt][3] - mn1);
                ps0 += p0 + p1;
                ps1 += p2 + p3;
                split2h(p0, p1, ph01[nt], pl01[nt]);
                split2h(p2, p3, ph23[nt], pl23[nt]);
            }
            ps0 += __shfl_xor_sync(0xffffffffu, ps0, 1);
            ps0 += __shfl_xor_sync(0xffffffffu, ps0, 2);
            ps1 += __shfl_xor_sync(0xffffffffu, ps1, 1);
            ps1 += __shfl_xor_sync(0xffffffffu, ps1, 2);
            l0 = l0 * corr0 + ps0;  m0 = mn0;
            l1 = l1 * corr1 + ps1;  m1 = mn1;
            #pragma unroll
            for (int nt = 0; nt < 8; nt++) {
                oacc[nt][0] *= corr0; oacc[nt][1] *= corr0;
                oacc[nt][2] *= corr1; oacc[nt][3] *= corr1;
            }

            // ---- O += P V (2 terms) ----
            #pragma unroll
            for (int kk = 0; kk < 4; kk++) {
                const uint32_t a0 = ph01[2*kk],   a1 = ph23[2*kk];
                const uint32_t a2 = ph01[2*kk+1], a3 = ph23[2*kk+1];
                const uint32_t c0 = pl01[2*kk],   c1 = pl23[2*kk];
                const uint32_t c2 = pl01[2*kk+1], c3 = pl23[2*kk+1];
                #pragma unroll
                for (int dp = 0; dp < 4; dp++) {
                    const int r = kk * 16 + (lane & 15);
                    const int d = dp * 16 + (lane >> 4) * 8;
                    const uint32_t off = r * 128 + (((d >> 3) ^ (r & 7)) << 4);
                    uint32_t b0a, b1a, b0b, b1b;
                    ldsm4t(b0a, b1a, b0b, b1b, uS + 8192 + off);   // Vh
                    mma16816(oacc[2*dp  ], a0, a1, a2, a3, b0a, b1a);
                    mma16816(oacc[2*dp+1], a0, a1, a2, a3, b0b, b1b);
                    mma16816(oacc[2*dp  ], c0, c1, c2, c3, b0a, b1a);
                    mma16816(oacc[2*dp+1], c0, c1, c2, c3, b0b, b1b);
                }
            }
        }
        stage++; if (stage == 3) stage = 0;
    }

    // ---- epilogue: normalize, split, write Y planes [B,T,C] ----
    f16* Yh = (f16*)g_Yh4;
    f16* Yl = (f16*)g_Yl4;
    const float inv0 = 1.0f / l0;
    const float inv1 = 1.0f / l1;
    const int b = bh >> 4, h = bh & 15;
    #pragma unroll
    for (int nt = 0; nt < 8; nt++) {
        const int coln = h * 64 + nt * 8 + tg * 2;
        uint32_t hp, lp;
        split2h(oacc[nt][0] * inv0, oacc[nt][1] * inv0, hp, lp);
        *(uint32_t*)&Yh[((size_t)(b*TT + row0))*CC + coln] = hp;
        *(uint32_t*)&Yl[((size_t)(b*TT + row0))*CC + coln] = lp;
        split2h(oacc[nt][2] * inv1, oacc[nt][3] * inv1, hp, lp);
        *(uint32_t*)&Yh[((size_t)(b*TT + row0 + 8))*CC + coln] = hp;
        *(uint32_t*)&Yl[((size_t)(b*TT + row0 + 8))*CC + coln] = lp;
    }
}

// ---------------------------------------------------------------------------
extern "C" void kernel_launch(void* const* d_in, const int* in_sizes, int n_in,
                              void* d_out, int out_size)
{
    const float* x      = (const float*)d_in[0];
    const float* b_attn = (const float*)d_in[2];
    const float* b_proj = (const float*)d_in[4];
    float* out = (float*)d_out;

    static bool attr_set = false;
    if (!attr_set) {
        cudaFuncSetAttribute(attn3_kernel,
                             cudaFuncAttributeMaxDynamicSharedMemorySize, ATT_SMEM);
        cudaFuncSetAttribute(hgemm_kernel<0>,
                             cudaFuncAttributeMaxDynamicSharedMemorySize, GEMM_SMEM);
        cudaFuncSetAttribute(hgemm_kernel<1>,
                             cudaFuncAttributeMaxDynamicSharedMemorySize, GEMM_SMEM);
        attr_set = true;
    }

    // 0) one-time fp32 -> fp16 conversion (x split; W single)
    convert_kernel<<<1024, 256>>>(x, (const float*)d_in[1], (const float*)d_in[3]);
    // 1) QKV GEMM (fp16 2-term) + scatter into Q(split)/K/V planes
    hgemm_kernel<0><<<dim3(3*CC/128, MM/128), 512, GEMM_SMEM>>>(b_attn, nullptr, 3*CC);
    // 2) Causal flash attention (fp16 2-term, 3-stage pipeline, longest-first)
    attn3_kernel<<<TT/128 * BB*HH, 256, ATT_SMEM>>>();
    // 3) Output projection (fp16 2-term)
    hgemm_kernel<1><<<dim3(CC/128, MM/128), 512, GEMM_SMEM>>>(b_proj, out, CC);
}